// round 14
// baseline (speedup 1.0000x reference)
#include <cuda_runtime.h>
#include <cuda_bf16.h>
#include <cstdint>

#define PATHS 4096
#define LPATH 8
#define DIM   256
#define HID   256
#define GATE  1024           // 4*HID
#define M1    (PATHS*LPATH)  // 32768
#define NODE  100000

// ---------------------------------------------------------------------------
// Scratch (static device globals; no runtime allocation)
// ---------------------------------------------------------------------------
__device__ float g_h[(size_t)PATHS * HID];
__device__ float g_c[(size_t)PATHS * HID];
__device__ float g_m[PATHS];
__device__ float g_a[PATHS];
__device__ float g_part[32 * HID];
__device__ float g_bias[GATE];                  // (b_ih + b_hh), permuted
__device__ int   g_is64;

// bf16 hi/lo split operands (K-major, row pitch = 256)
// Weight rows PERMUTED: new row = 4*unit + gate  (gate: 0=i,1=f,2=g,3=o)
__device__ __align__(256) __nv_bfloat16 g_Xhi[(size_t)M1 * DIM];
__device__ __align__(256) __nv_bfloat16 g_Xlo[(size_t)M1 * DIM];
__device__ __align__(256) __nv_bfloat16 g_Hhi[(size_t)PATHS * HID];
__device__ __align__(256) __nv_bfloat16 g_Hlo[(size_t)PATHS * HID];
__device__ __align__(256) __nv_bfloat16 g_Wihhi[(size_t)GATE * DIM];
__device__ __align__(256) __nv_bfloat16 g_Wihlo[(size_t)GATE * DIM];
__device__ __align__(256) __nv_bfloat16 g_Whhhi[(size_t)GATE * HID];
__device__ __align__(256) __nv_bfloat16 g_Whhlo[(size_t)GATE * HID];

// ---------------------------------------------------------------------------
// PTX helpers (base-target, assembles for family-generic sm_103)
// ---------------------------------------------------------------------------
__device__ __forceinline__ uint32_t smem_to_u32(const void* p) {
    uint32_t a;
    asm("{ .reg .u64 t; cvta.to.shared.u64 t, %1; cvt.u32.u64 %0, t; }"
        : "=r"(a) : "l"(p));
    return a;
}

__device__ __forceinline__ void ldmx4(uint32_t addr, uint32_t* r) {
    asm volatile("ldmatrix.sync.aligned.m8n8.x4.shared.b16 {%0,%1,%2,%3}, [%4];"
                 : "=r"(r[0]), "=r"(r[1]), "=r"(r[2]), "=r"(r[3]) : "r"(addr));
}

__device__ __forceinline__ void mma16816(float* d, const uint32_t* a,
                                         uint32_t b0, uint32_t b1) {
    asm volatile(
        "mma.sync.aligned.m16n8k16.row.col.f32.bf16.bf16.f32 "
        "{%0,%1,%2,%3}, {%4,%5,%6,%7}, {%8,%9}, {%0,%1,%2,%3};"
        : "+f"(d[0]), "+f"(d[1]), "+f"(d[2]), "+f"(d[3])
        : "r"(a[0]), "r"(a[1]), "r"(a[2]), "r"(a[3]), "r"(b0), "r"(b1));
}

__device__ __forceinline__ void cpasync16(uint32_t dst, const void* src) {
    asm volatile("cp.async.cg.shared.global [%0], [%1], 16;"
                 :: "r"(dst), "l"(src) : "memory");
}
#define CP_COMMIT() asm volatile("cp.async.commit_group;" ::: "memory")
#define CP_WAIT0()  asm volatile("cp.async.wait_group 0;" ::: "memory")

// ---------------------------------------------------------------------------
// Index-dtype probe (int64 reference vs possible int32 materialization)
// ---------------------------------------------------------------------------
__global__ void detect_idx_kernel(const void* __restrict__ paths_raw)
{
    const int* a = (const int*)paths_raw;
    int ok64 = 1;
#pragma unroll
    for (int i = 0; i < 64; i += 2)
        if (a[i + 1] != 0) ok64 = 0;
    g_is64 = ok64;
}

__device__ __forceinline__ long long load_idx(const void* buf, int m)
{
    if (g_is64) return ((const long long*)buf)[m];
    return (long long)((const int*)buf)[m];
}

// ---------------------------------------------------------------------------
// Precision-split conversions
// ---------------------------------------------------------------------------
__device__ __forceinline__ void split_bf16(float x, __nv_bfloat16& hi, __nv_bfloat16& lo)
{
    hi = __float2bfloat16(x);
    lo = __float2bfloat16(x - __bfloat162float(hi));
}

// weights -> hi/lo bf16 with gate-interleave row permutation
__global__ void conv_w(const float* __restrict__ w_ih, const float* __restrict__ w_hh)
{
    const int idx = blockIdx.x * blockDim.x + threadIdx.x;  // 0 .. 2*262144-1
    const int half = idx >= GATE * DIM;
    const int j    = half ? idx - GATE * DIM : idx;
    const int r    = j >> 8;                 // original row
    const int c    = j & 255;
    const int newr = ((r & 255) << 2) | (r >> 8);   // 4*unit + gate
    const int dst  = (newr << 8) | c;
    if (!half) split_bf16(w_ih[j], g_Wihhi[dst], g_Wihlo[dst]);
    else       split_bf16(w_hh[j], g_Whhhi[dst], g_Whhlo[dst]);
}

__global__ void bias_perm(const float* __restrict__ b_ih, const float* __restrict__ b_hh)
{
    const int r = blockIdx.x * blockDim.x + threadIdx.x;   // 0..1023 original
    const int newr = ((r & 255) << 2) | (r >> 8);
    g_bias[newr] = b_ih[r] + b_hh[r];
}

// gather embedding rows -> hi/lo bf16 (float4 per thread, 4 rows per block)
__global__ void gather_conv(const float* __restrict__ emb, const void* __restrict__ paths)
{
    const int tid = threadIdx.x;              // 256
    const int m   = blockIdx.x * 4 + (tid >> 6);
    const int c4  = (tid & 63) << 2;
    const size_t row = (size_t)load_idx(paths, m);
    const float4 x = *(const float4*)(emb + row * DIM + c4);
    __nv_bfloat16 h0, l0, h1, l1, h2, l2, h3, l3;
    split_bf16(x.x, h0, l0); split_bf16(x.y, h1, l1);
    split_bf16(x.z, h2, l2); split_bf16(x.w, h3, l3);
    const __nv_bfloat162 hA = {h0, h1}, hB = {h2, h3};
    const __nv_bfloat162 lA = {l0, l1}, lB = {l2, l3};
    __nv_bfloat162* dh = (__nv_bfloat162*)(g_Xhi + (size_t)m * DIM + c4);
    __nv_bfloat162* dl = (__nv_bfloat162*)(g_Xlo + (size_t)m * DIM + c4);
    dh[0] = hA; dh[1] = hB;
    dl[0] = lA; dl[1] = lB;
}

// ---------------------------------------------------------------------------
// Concat-K recurrent step GEMM, bf16 HMMA hi/lo split.
//   gates_t = [h | x_t] @ [w_hh | w_ih]^T + bias  (K = 512), fused LSTM cell.
// BM=128, BN=128, KC=32, 2-stage cp.async, 256 threads (8 warps, 2x4),
// warp tile 64x32, smem 2 x 40KB, 2 CTAs/SM.
// ---------------------------------------------------------------------------
#define PITCH_B 80                     // bytes per smem row (40 bf16)
#define MAT_SZ  (128 * PITCH_B)        // 10240 bytes per matrix
#define STG_SZ  (4 * MAT_SZ)           // 40960 per stage
#define SM_TOT  (2 * STG_SZ)           // 81920
#define OFF_AHI 0
#define OFF_ALO MAT_SZ
#define OFF_BHI (2 * MAT_SZ)
#define OFF_BLO (3 * MAT_SZ)

__device__ __forceinline__ float sigf(float x) { return 1.f / (1.f + expf(-x)); }

// Load one KC=32 chunk (all 4 matrices) into one stage. 256 threads:
// row = tid>>1 (0..127), half = tid&1 selects 32B half-row. All indexing static.
__device__ __forceinline__ void stage_load(
    uint32_t sbase,
    const __nv_bfloat16* __restrict__ aH, const __nv_bfloat16* __restrict__ aL,
    const __nv_bfloat16* __restrict__ bH, const __nv_bfloat16* __restrict__ bL,
    size_t astr, int tid)
{
    const int row  = tid >> 1;
    const int half = tid & 1;
    const uint32_t rb = (uint32_t)row * PITCH_B + half * 32;
    const size_t ao = (size_t)row * astr + half * 16;
    const size_t bo = (size_t)row * DIM  + half * 16;
    cpasync16(sbase + OFF_AHI + rb,      aH + ao);
    cpasync16(sbase + OFF_AHI + rb + 16, aH + ao + 8);
    cpasync16(sbase + OFF_ALO + rb,      aL + ao);
    cpasync16(sbase + OFF_ALO + rb + 16, aL + ao + 8);
    cpasync16(sbase + OFF_BHI + rb,      bH + bo);
    cpasync16(sbase + OFF_BHI + rb + 16, bH + bo + 8);
    cpasync16(sbase + OFF_BLO + rb,      bL + bo);
    cpasync16(sbase + OFF_BLO + rb + 16, bL + bo + 8);
}

__global__ void __launch_bounds__(256, 2)
mm_step(int t)
{
    extern __shared__ char smem[];
    const uint32_t sb = smem_to_u32(smem);
    const int tid  = threadIdx.x;
    const int bx   = blockIdx.x;   // N tile (0..7), 128 cols
    const int by   = blockIdx.y;   // M tile (0..31), 128 paths

    const size_t arow0 = (size_t)by * 128;   // path offset
    const size_t brow0 = (size_t)bx * 128;   // (permuted) gate-row offset

    // chunk-kc source pointers: k<256 -> h/w_hh, k>=256 -> x_t/w_ih
    auto srcs = [&](int kc, const __nv_bfloat16*& aH, const __nv_bfloat16*& aL,
                    const __nv_bfloat16*& bH, const __nv_bfloat16*& bL, size_t& astr) {
        const int k0 = kc * 32;
        if (k0 < 256) {
            aH = g_Hhi + arow0 * HID + k0;
            aL = g_Hlo + arow0 * HID + k0;
            bH = g_Whhhi + brow0 * HID + k0;
            bL = g_Whhlo + brow0 * HID + k0;
            astr = HID;
        } else {
            const int kx = k0 - 256;
            const size_t xr = (arow0 * LPATH + t) * DIM;
            aH = g_Xhi + xr + kx;
            aL = g_Xlo + xr + kx;
            bH = g_Wihhi + brow0 * DIM + kx;
            bL = g_Wihlo + brow0 * DIM + kx;
            astr = (size_t)LPATH * DIM;
        }
    };

    // ---- warp tiling: 8 warps = 2 (m) x 4 (n), warp tile 64x32 ----
    const int wid  = tid >> 5;
    const int lane = tid & 31;
    const int wm   = wid & 1;
    const int wn   = wid >> 1;         // 0..3
    const int lr   = lane & 7;
    const int lg   = lane >> 3;

    const uint32_t aoff = (uint32_t)(wm * 64 + (lg & 1) * 8 + lr) * PITCH_B + (lg >> 1) * 16;
    const uint32_t boff = (uint32_t)(wn * 32 + (lg >> 1) * 8 + lr) * PITCH_B + (lg & 1) * 16;

    float acc[4][4][4];
#pragma unroll
    for (int i = 0; i < 4; i++)
#pragma unroll
        for (int j = 0; j < 4; j++)
#pragma unroll
            for (int d = 0; d < 4; d++) acc[i][j][d] = 0.f;

    // ---- prologue: stage 0 ----
    {
        const __nv_bfloat16 *aH, *aL, *bH, *bL; size_t astr;
        srcs(0, aH, aL, bH, bL, astr);
        stage_load(sb, aH, aL, bH, bL, astr, tid);
        CP_COMMIT();
    }

    for (int kc = 0; kc < 16; kc++) {
        CP_WAIT0();
        __syncthreads();

        if (kc + 1 < 16) {
            const __nv_bfloat16 *aH, *aL, *bH, *bL; size_t astr;
            srcs(kc + 1, aH, aL, bH, bL, astr);
            stage_load(sb + ((kc + 1) & 1) * STG_SZ, aH, aL, bH, bL, astr, tid);
            CP_COMMIT();
        }

        const uint32_t st = sb + (kc & 1) * STG_SZ;
#pragma unroll
        for (int k16 = 0; k16 < 2; k16++) {
            const uint32_t ko = k16 * 32;
            uint32_t ah[4][4], al[4][4], b[2][4];
#pragma unroll
            for (int mt = 0; mt < 4; mt++) {
                ldmx4(st + OFF_AHI + aoff + ko + mt * (16 * PITCH_B), ah[mt]);
                ldmx4(st + OFF_ALO + aoff + ko + mt * (16 * PITCH_B), al[mt]);
            }
            // B hi: Ah*Bh and Al*Bh
#pragma unroll
            for (int bt = 0; bt < 2; bt++)
                ldmx4(st + OFF_BHI + boff + ko + bt * (16 * PITCH_B), b[bt]);
#pragma unroll
            for (int mt = 0; mt < 4; mt++)
#pragma unroll
                for (int bt = 0; bt < 2; bt++)
#pragma unroll
                    for (int sub = 0; sub < 2; sub++) {
                        mma16816(acc[mt][bt * 2 + sub], ah[mt], b[bt][2 * sub], b[bt][2 * sub + 1]);
                        mma16816(acc[mt][bt * 2 + sub], al[mt], b[bt][2 * sub], b[bt][2 * sub + 1]);
                    }
            // B lo: Ah*Bl (reuse b regs)
#pragma unroll
            for (int bt = 0; bt < 2; bt++)
                ldmx4(st + OFF_BLO + boff + ko + bt * (16 * PITCH_B), b[bt]);
#pragma unroll
            for (int mt = 0; mt < 4; mt++)
#pragma unroll
                for (int bt = 0; bt < 2; bt++)
#pragma unroll
                    for (int sub = 0; sub < 2; sub++)
                        mma16816(acc[mt][bt * 2 + sub], ah[mt], b[bt][2 * sub], b[bt][2 * sub + 1]);
        }
    }

    // ---- epilogue: +bias, fused LSTM cell ----
    const int lq = lane >> 2;            // row within 8
    const int lp = lane & 3;             // col pair within n8
#pragma unroll
    for (int mt = 0; mt < 4; mt++) {
#pragma unroll
        for (int nt = 0; nt < 4; nt++) {
            const int gcol = bx * 128 + wn * 32 + nt * 8 + lp * 2;
            const float bias0 = g_bias[gcol];
            const float bias1 = g_bias[gcol + 1];
#pragma unroll
            for (int half = 0; half < 2; half++) {
                const int rloc = wm * 64 + mt * 16 + lq + half * 8;
                const size_t m = arow0 + rloc;
                float v0 = acc[mt][nt][half * 2 + 0] + bias0;
                float v1 = acc[mt][nt][half * 2 + 1] + bias1;
                // assemble (i,f,g,o) quad across lane pair (lp even: i,f / odd: g,o)
                const float w0 = __shfl_xor_sync(0xffffffffu, v0, 1);
                const float w1 = __shfl_xor_sync(0xffffffffu, v1, 1);
                float iv, fv, gv, ov;
                if (lp & 1) { iv = w0; fv = w1; gv = v0; ov = v1; }
                else        { iv = v0; fv = v1; gv = w0; ov = w1; }
                const int unit = gcol >> 2;           // same for both lanes of pair
                const size_t idx = m * HID + unit;
                const float cold = g_c[idx];
                const float cnew = sigf(fv) * cold + sigf(iv) * tanhf(gv);
                const float h    = sigf(ov) * tanhf(cnew);
                if (lp & 1) {
                    __nv_bfloat16 hh, hl;
                    split_bf16(h, hh, hl);
                    g_Hhi[idx] = hh;
                    g_Hlo[idx] = hl;
                } else {
                    g_c[idx] = cnew;
                    g_h[idx] = h;
                }
            }
        }
    }
}

__global__ void zero_hc()
{
    const int idx = blockIdx.x * blockDim.x + threadIdx.x;
    g_c[idx] = 0.f;
    g_Hhi[idx] = __float2bfloat16(0.f);
    g_Hlo[idx] = __float2bfloat16(0.f);
}

// ---- row-max over hidden dim: one warp per path ----
__global__ void rowmax()
{
    const int w    = (blockIdx.x * blockDim.x + threadIdx.x) >> 5;
    const int lane = threadIdx.x & 31;
    const float* hr = g_h + (size_t)w * HID;
    float v = -1e30f;
#pragma unroll
    for (int k = lane; k < HID; k += 32) v = fmaxf(v, hr[k]);
#pragma unroll
    for (int o = 16; o > 0; o >>= 1)
        v = fmaxf(v, __shfl_xor_sync(0xffffffffu, v, o));
    if (lane == 0) g_m[w] = v;
}

// ---- softmax over 4096 path logits (single block, deterministic) ----
__global__ void softmax_paths()
{
    __shared__ float red[32];
    __shared__ float bcast;
    const int tid  = threadIdx.x;
    const int lane = tid & 31, wid = tid >> 5;

    float v[4];
    float mx = -1e30f;
#pragma unroll
    for (int i = 0; i < 4; i++) {
        v[i] = g_m[tid + i * 1024];
        mx = fmaxf(mx, v[i]);
    }
#pragma unroll
    for (int o = 16; o > 0; o >>= 1)
        mx = fmaxf(mx, __shfl_xor_sync(0xffffffffu, mx, o));
    if (lane == 0) red[wid] = mx;
    __syncthreads();
    if (wid == 0) {
        float m2 = red[lane];
#pragma unroll
        for (int o = 16; o > 0; o >>= 1)
            m2 = fmaxf(m2, __shfl_xor_sync(0xffffffffu, m2, o));
        if (lane == 0) bcast = m2;
    }
    __syncthreads();
    const float MX = bcast;

    float s = 0.f;
#pragma unroll
    for (int i = 0; i < 4; i++) { v[i] = expf(v[i] - MX); s += v[i]; }
#pragma unroll
    for (int o = 16; o > 0; o >>= 1)
        s += __shfl_xor_sync(0xffffffffu, s, o);
    if (lane == 0) red[wid] = s;
    __syncthreads();
    if (wid == 0) {
        float s2 = red[lane];
#pragma unroll
        for (int o = 16; o > 0; o >>= 1)
            s2 += __shfl_xor_sync(0xffffffffu, s2, o);
        if (lane == 0) bcast = s2;
    }
    __syncthreads();
    const float inv = 1.f / bcast;
#pragma unroll
    for (int i = 0; i < 4; i++) g_a[tid + i * 1024] = v[i] * inv;
}

// ---- weighted column sum: partials per 128-path chunk (no atomics) ----
__global__ void wsum()
{
    const int col = threadIdx.x;
    const int p0  = blockIdx.x * 128;
    float acc = 0.f;
    for (int pp = 0; pp < 128; pp++) {
        const int p = p0 + pp;
        acc += g_h[(size_t)p * HID + col] * g_a[p];
    }
    g_part[blockIdx.x * HID + col] = acc;
}

// ---- final: reduce partials, concat dot with w_lin, sigmoid ----
__global__ void final_k(const float* __restrict__ emb,
                        const void* __restrict__ uid,
                        const void* __restrict__ iid,
                        const float* __restrict__ w_lin,
                        const float* __restrict__ b_lin,
                        float* __restrict__ out)
{
    __shared__ float red[256];
    const int j = threadIdx.x;
    float pe = 0.f;
#pragma unroll
    for (int b = 0; b < 32; b++) pe += g_part[b * HID + j];

    const size_t u  = (size_t)load_idx(uid, 0) * DIM;
    const size_t it = (size_t)load_idx(iid, 0) * DIM;
    float v = emb[u + j]  * w_lin[j]
            + emb[it + j] * w_lin[256 + j]
            + pe          * w_lin[512 + j];
    red[j] = v;
    __syncthreads();
#pragma unroll
    for (int s = 128; s > 0; s >>= 1) {
        if (j < s) red[j] += red[j + s];
        __syncthreads();
    }
    if (j == 0) out[0] = 1.f / (1.f + expf(-(red[0] + b_lin[0])));
}

extern "C" void kernel_launch(void* const* d_in, const int* in_sizes, int n_in,
                              void* d_out, int out_size)
{
    const float* embedding = (const float*)d_in[0];
    const float* w_ih      = (const float*)d_in[1];
    const float* w_hh      = (const float*)d_in[2];
    const float* b_ih      = (const float*)d_in[3];
    const float* b_hh      = (const float*)d_in[4];
    const float* w_lin     = (const float*)d_in[5];
    const float* b_lin     = (const float*)d_in[6];
    const void*  paths     = d_in[7];
    const void*  uid       = d_in[8];
    const void*  iid       = d_in[9];

    cudaFuncSetAttribute(mm_step, cudaFuncAttributeMaxDynamicSharedMemorySize, SM_TOT);

    detect_idx_kernel<<<1, 1>>>(paths);
    zero_hc<<<PATHS, 256>>>();
    conv_w<<<2 * GATE * DIM / 256, 256>>>(w_ih, w_hh);
    bias_perm<<<4, 256>>>(b_ih, b_hh);
    gather_conv<<<M1 / 4, 256>>>(embedding, paths);

    // 8 fused steps: gates_t = [h | x_t] @ [w_hh | w_ih]^T + bias, LSTM in epilogue
    for (int t = 0; t < LPATH; t++)
        mm_step<<<dim3(8, PATHS / 128), 256, SM_TOT>>>(t);

    // attention over paths + final linear/sigmoid
    rowmax<<<512, 256>>>();
    softmax_paths<<<1, 1024>>>();
    wsum<<<32, 256>>>();
    final_k<<<1, 256>>>(embedding, uid, iid, w_lin, b_lin, (float*)d_out);
}

// round 15
// speedup vs baseline: 1.3288x; 1.3288x over previous
#include <cuda_runtime.h>
#include <cuda_bf16.h>
#include <cstdint>

#define PATHS 4096
#define LPATH 8
#define DIM   256
#define HID   256
#define GATE  1024           // 4*HID
#define M1    (PATHS*LPATH)  // 32768
#define NODE  100000

// ---------------------------------------------------------------------------
// Scratch (static device globals; no runtime allocation)
// ---------------------------------------------------------------------------
__device__ float g_X[(size_t)M1 * GATE];        // input projections (+bias), fp32,
                                                // columns in PERMUTED gate order 4*unit+gate
__device__ float g_h[(size_t)PATHS * HID];
__device__ float g_c[(size_t)PATHS * HID];
__device__ float g_m[PATHS];
__device__ float g_a[PATHS];
__device__ float g_part[32 * HID];
__device__ float g_bias[GATE];                  // (b_ih + b_hh), permuted
__device__ int   g_is64;

// bf16 hi/lo split operands (K-major, row pitch = 256)
// Weight rows PERMUTED: new row = 4*unit + gate  (gate: 0=i,1=f,2=g,3=o)
__device__ __align__(256) __nv_bfloat16 g_Xhi[(size_t)M1 * DIM];
__device__ __align__(256) __nv_bfloat16 g_Xlo[(size_t)M1 * DIM];
__device__ __align__(256) __nv_bfloat16 g_Hhi[(size_t)PATHS * HID];
__device__ __align__(256) __nv_bfloat16 g_Hlo[(size_t)PATHS * HID];
__device__ __align__(256) __nv_bfloat16 g_Wihhi[(size_t)GATE * DIM];
__device__ __align__(256) __nv_bfloat16 g_Wihlo[(size_t)GATE * DIM];
__device__ __align__(256) __nv_bfloat16 g_Whhhi[(size_t)GATE * HID];
__device__ __align__(256) __nv_bfloat16 g_Whhlo[(size_t)GATE * HID];

// ---------------------------------------------------------------------------
// PTX helpers (base-target, assembles for family-generic sm_103)
// ---------------------------------------------------------------------------
__device__ __forceinline__ uint32_t smem_to_u32(const void* p) {
    uint32_t a;
    asm("{ .reg .u64 t; cvta.to.shared.u64 t, %1; cvt.u32.u64 %0, t; }"
        : "=r"(a) : "l"(p));
    return a;
}

__device__ __forceinline__ void ldmx4(uint32_t addr, uint32_t* r) {
    asm volatile("ldmatrix.sync.aligned.m8n8.x4.shared.b16 {%0,%1,%2,%3}, [%4];"
                 : "=r"(r[0]), "=r"(r[1]), "=r"(r[2]), "=r"(r[3]) : "r"(addr));
}

__device__ __forceinline__ void mma16816(float* d, const uint32_t* a,
                                         uint32_t b0, uint32_t b1) {
    asm volatile(
        "mma.sync.aligned.m16n8k16.row.col.f32.bf16.bf16.f32 "
        "{%0,%1,%2,%3}, {%4,%5,%6,%7}, {%8,%9}, {%0,%1,%2,%3};"
        : "+f"(d[0]), "+f"(d[1]), "+f"(d[2]), "+f"(d[3])
        : "r"(a[0]), "r"(a[1]), "r"(a[2]), "r"(a[3]), "r"(b0), "r"(b1));
}

__device__ __forceinline__ void cpasync16(uint32_t dst, const void* src) {
    asm volatile("cp.async.cg.shared.global [%0], [%1], 16;"
                 :: "r"(dst), "l"(src) : "memory");
}
#define CP_COMMIT() asm volatile("cp.async.commit_group;" ::: "memory")
#define CP_WAIT0()  asm volatile("cp.async.wait_group 0;" ::: "memory")

// ---------------------------------------------------------------------------
// Index-dtype probe (int64 reference vs possible int32 materialization)
// ---------------------------------------------------------------------------
__global__ void detect_idx_kernel(const void* __restrict__ paths_raw)
{
    const int* a = (const int*)paths_raw;
    int ok64 = 1;
#pragma unroll
    for (int i = 0; i < 64; i += 2)
        if (a[i + 1] != 0) ok64 = 0;
    g_is64 = ok64;
}

__device__ __forceinline__ long long load_idx(const void* buf, int m)
{
    if (g_is64) return ((const long long*)buf)[m];
    return (long long)((const int*)buf)[m];
}

// ---------------------------------------------------------------------------
// Precision-split conversions
// ---------------------------------------------------------------------------
__device__ __forceinline__ void split_bf16(float x, __nv_bfloat16& hi, __nv_bfloat16& lo)
{
    hi = __float2bfloat16(x);
    lo = __float2bfloat16(x - __bfloat162float(hi));
}

// ---------------------------------------------------------------------------
// prep: weights->hi/lo bf16 (permuted rows), bias (permuted), zero h/c state.
// One kernel, role by blockIdx.x:
//   [0, 2048)      : conv_w   (2*GATE*DIM elems)
//   [2048, 2052)   : bias_perm
//   [2052, 6148)   : zero g_c / g_Hhi / g_Hlo (PATHS*HID elems)
// ---------------------------------------------------------------------------
__global__ void prep(const float* __restrict__ w_ih, const float* __restrict__ w_hh,
                     const float* __restrict__ b_ih, const float* __restrict__ b_hh)
{
    const int b = blockIdx.x;
    const int tid = threadIdx.x;
    if (b < 2048) {
        const int idx = b * 256 + tid;
        const int half = idx >= GATE * DIM;
        const int j    = half ? idx - GATE * DIM : idx;
        const int r    = j >> 8;
        const int c    = j & 255;
        const int newr = ((r & 255) << 2) | (r >> 8);   // 4*unit + gate
        const int dst  = (newr << 8) | c;
        if (!half) split_bf16(w_ih[j], g_Wihhi[dst], g_Wihlo[dst]);
        else       split_bf16(w_hh[j], g_Whhhi[dst], g_Whhlo[dst]);
    } else if (b < 2052) {
        const int r = (b - 2048) * 256 + tid;
        const int newr = ((r & 255) << 2) | (r >> 8);
        g_bias[newr] = b_ih[r] + b_hh[r];
    } else {
        const int idx = (b - 2052) * 256 + tid;
        g_c[idx] = 0.f;
        g_Hhi[idx] = __float2bfloat16(0.f);
        g_Hlo[idx] = __float2bfloat16(0.f);
    }
}

// gather embedding rows -> hi/lo bf16 (float4 per thread, 4 rows per block)
__global__ void gather_conv(const float* __restrict__ emb, const void* __restrict__ paths)
{
    const int tid = threadIdx.x;              // 256
    const int m   = blockIdx.x * 4 + (tid >> 6);
    const int c4  = (tid & 63) << 2;
    const size_t row = (size_t)load_idx(paths, m);
    const float4 x = *(const float4*)(emb + row * DIM + c4);
    __nv_bfloat16 h0, l0, h1, l1, h2, l2, h3, l3;
    split_bf16(x.x, h0, l0); split_bf16(x.y, h1, l1);
    split_bf16(x.z, h2, l2); split_bf16(x.w, h3, l3);
    const __nv_bfloat162 hA = {h0, h1}, hB = {h2, h3};
    const __nv_bfloat162 lA = {l0, l1}, lB = {l2, l3};
    __nv_bfloat162* dh = (__nv_bfloat162*)(g_Xhi + (size_t)m * DIM + c4);
    __nv_bfloat162* dl = (__nv_bfloat162*)(g_Xlo + (size_t)m * DIM + c4);
    dh[0] = hA; dh[1] = hB;
    dl[0] = lA; dl[1] = lB;
}

// ---------------------------------------------------------------------------
// Fused per-hop GEMM launch. Two roles, selected by blockIdx.y:
//   STEP  (t in 0..7):  gates = h @ w_hh^T + g_X[:,t,:]  -> fused LSTM cell
//   SLICE (hop in 0..7): g_X[:,hop,:] = x_hop @ w_ih^T + bias
// Launch t carries step(t) [y<32] and slice(t+1) [y>=32]; t=-1 is slice(0)
// only; t=7 is step only.
// BM=128, BN=128, KC=32, 2-stage cp.async, 256 threads (8 warps, 2x4),
// warp tile 64x32, smem 2 x 40KB, 2 CTAs/SM.
// ---------------------------------------------------------------------------
#define PITCH_B 80                     // bytes per smem row (40 bf16)
#define MAT_SZ  (128 * PITCH_B)        // 10240 bytes per matrix
#define STG_SZ  (4 * MAT_SZ)           // 40960 per stage
#define SM_TOT  (2 * STG_SZ)           // 81920
#define OFF_AHI 0
#define OFF_ALO MAT_SZ
#define OFF_BHI (2 * MAT_SZ)
#define OFF_BLO (3 * MAT_SZ)

__device__ __forceinline__ float sigf(float x) { return 1.f / (1.f + expf(-x)); }

// Load one KC=32 chunk (all 4 matrices) into one stage. 256 threads:
// row = tid>>1 (0..127), half = tid&1 selects 32B half-row. All static.
__device__ __forceinline__ void stage_load(
    uint32_t sbase,
    const __nv_bfloat16* __restrict__ aH, const __nv_bfloat16* __restrict__ aL,
    const __nv_bfloat16* __restrict__ bH, const __nv_bfloat16* __restrict__ bL,
    size_t astr, int tid)
{
    const int row  = tid >> 1;
    const int half = tid & 1;
    const uint32_t rb = (uint32_t)row * PITCH_B + half * 32;
    const size_t ao = (size_t)row * astr + half * 16;
    const size_t bo = (size_t)row * 256  + half * 16;
    cpasync16(sbase + OFF_AHI + rb,      aH + ao);
    cpasync16(sbase + OFF_AHI + rb + 16, aH + ao + 8);
    cpasync16(sbase + OFF_ALO + rb,      aL + ao);
    cpasync16(sbase + OFF_ALO + rb + 16, aL + ao + 8);
    cpasync16(sbase + OFF_BHI + rb,      bH + bo);
    cpasync16(sbase + OFF_BHI + rb + 16, bH + bo + 8);
    cpasync16(sbase + OFF_BLO + rb,      bL + bo);
    cpasync16(sbase + OFF_BLO + rb + 16, bL + bo + 8);
}

__global__ void __launch_bounds__(256, 2)
mm_fused(int t)
{
    extern __shared__ char smem[];
    const uint32_t sb = smem_to_u32(smem);
    const int tid  = threadIdx.x;
    const int bx   = blockIdx.x;   // N tile (0..7), 128 cols
    const int byr  = blockIdx.y;

    bool is_step;
    int  hop = 0;
    int  tile;
    if (t < 0)            { is_step = false; hop = 0;     tile = byr; }
    else if (t == 7)      { is_step = true;               tile = byr; }
    else if (byr < 32)    { is_step = true;               tile = byr; }
    else                  { is_step = false; hop = t + 1; tile = byr - 32; }

    const size_t arow0 = (size_t)tile * 128;   // path offset
    const size_t brow0 = (size_t)bx * 128;     // (permuted) gate-row offset

    const __nv_bfloat16 *aHb, *aLb, *bHb, *bLb;
    size_t astr;
    if (is_step) {
        aHb = g_Hhi + arow0 * HID;
        aLb = g_Hlo + arow0 * HID;
        bHb = g_Whhhi + brow0 * HID;
        bLb = g_Whhlo + brow0 * HID;
        astr = HID;
    } else {
        aHb = g_Xhi + (arow0 * LPATH + hop) * DIM;
        aLb = g_Xlo + (arow0 * LPATH + hop) * DIM;
        bHb = g_Wihhi + brow0 * DIM;
        bLb = g_Wihlo + brow0 * DIM;
        astr = (size_t)LPATH * DIM;
    }

    // ---- warp tiling: 8 warps = 2 (m) x 4 (n), warp tile 64x32 ----
    const int wid  = tid >> 5;
    const int lane = tid & 31;
    const int wm   = wid & 1;
    const int wn   = wid >> 1;         // 0..3
    const int lr   = lane & 7;
    const int lg   = lane >> 3;

    const uint32_t aoff = (uint32_t)(wm * 64 + (lg & 1) * 8 + lr) * PITCH_B + (lg >> 1) * 16;
    const uint32_t boff = (uint32_t)(wn * 32 + (lg >> 1) * 8 + lr) * PITCH_B + (lg & 1) * 16;

    float acc[4][4][4];
#pragma unroll
    for (int i = 0; i < 4; i++)
#pragma unroll
        for (int j = 0; j < 4; j++)
#pragma unroll
            for (int d = 0; d < 4; d++) acc[i][j][d] = 0.f;

    // ---- prologue: stage 0 ----
    stage_load(sb, aHb, aLb, bHb, bLb, astr, tid);
    CP_COMMIT();

    for (int kc = 0; kc < 8; kc++) {
        CP_WAIT0();
        __syncthreads();

        if (kc + 1 < 8) {
            const int k0 = (kc + 1) * 32;
            stage_load(sb + ((kc + 1) & 1) * STG_SZ,
                       aHb + k0, aLb + k0, bHb + k0, bLb + k0, astr, tid);
            CP_COMMIT();
        }

        const uint32_t st = sb + (kc & 1) * STG_SZ;
#pragma unroll
        for (int k16 = 0; k16 < 2; k16++) {
            const uint32_t ko = k16 * 32;
            uint32_t ah[4][4], al[4][4], b[2][4];
#pragma unroll
            for (int mt = 0; mt < 4; mt++) {
                ldmx4(st + OFF_AHI + aoff + ko + mt * (16 * PITCH_B), ah[mt]);
                ldmx4(st + OFF_ALO + aoff + ko + mt * (16 * PITCH_B), al[mt]);
            }
            // B hi: Ah*Bh and Al*Bh
#pragma unroll
            for (int bt = 0; bt < 2; bt++)
                ldmx4(st + OFF_BHI + boff + ko + bt * (16 * PITCH_B), b[bt]);
#pragma unroll
            for (int mt = 0; mt < 4; mt++)
#pragma unroll
                for (int bt = 0; bt < 2; bt++)
#pragma unroll
                    for (int sub = 0; sub < 2; sub++) {
                        mma16816(acc[mt][bt * 2 + sub], ah[mt], b[bt][2 * sub], b[bt][2 * sub + 1]);
                        mma16816(acc[mt][bt * 2 + sub], al[mt], b[bt][2 * sub], b[bt][2 * sub + 1]);
                    }
            // B lo: Ah*Bl (reuse b regs)
#pragma unroll
            for (int bt = 0; bt < 2; bt++)
                ldmx4(st + OFF_BLO + boff + ko + bt * (16 * PITCH_B), b[bt]);
#pragma unroll
            for (int mt = 0; mt < 4; mt++)
#pragma unroll
                for (int bt = 0; bt < 2; bt++)
#pragma unroll
                    for (int sub = 0; sub < 2; sub++)
                        mma16816(acc[mt][bt * 2 + sub], ah[mt], b[bt][2 * sub], b[bt][2 * sub + 1]);
        }
    }

    // ---- epilogue ----
    const int lq = lane >> 2;            // row within 8
    const int lp = lane & 3;             // col pair within n8
#pragma unroll
    for (int mt = 0; mt < 4; mt++) {
#pragma unroll
        for (int nt = 0; nt < 4; nt++) {
            const int gcol = bx * 128 + wn * 32 + nt * 8 + lp * 2;
#pragma unroll
            for (int half = 0; half < 2; half++) {
                const int rloc = wm * 64 + mt * 16 + lq + half * 8;
                const size_t m = arow0 + rloc;
                float v0 = acc[mt][nt][half * 2 + 0];
                float v1 = acc[mt][nt][half * 2 + 1];
                if (!is_step) {
                    v0 += g_bias[gcol];
                    v1 += g_bias[gcol + 1];
                    *(float2*)(g_X + (m * LPATH + hop) * GATE + gcol) = make_float2(v0, v1);
                } else {
                    const float2 ad = *(const float2*)(g_X + (m * LPATH + t) * GATE + gcol);
                    v0 += ad.x;
                    v1 += ad.y;
                    // assemble (i,f,g,o) quad across lane pair (lp even: i,f / odd: g,o)
                    const float w0 = __shfl_xor_sync(0xffffffffu, v0, 1);
                    const float w1 = __shfl_xor_sync(0xffffffffu, v1, 1);
                    float iv, fv, gv, ov;
                    if (lp & 1) { iv = w0; fv = w1; gv = v0; ov = v1; }
                    else        { iv = v0; fv = v1; gv = w0; ov = w1; }
                    const int unit = gcol >> 2;           // same for both lanes of pair
                    const size_t idx = m * HID + unit;
                    const float cold = g_c[idx];
                    const float cnew = sigf(fv) * cold + sigf(iv) * tanhf(gv);
                    const float h    = sigf(ov) * tanhf(cnew);
                    if (lp & 1) {
                        __nv_bfloat16 hh, hl;
                        split_bf16(h, hh, hl);
                        g_Hhi[idx] = hh;
                        g_Hlo[idx] = hl;
                    } else {
                        g_c[idx] = cnew;
                        g_h[idx] = h;
                    }
                }
            }
        }
    }
}

// ---- row-max over hidden dim: one warp per path ----
__global__ void rowmax()
{
    const int w    = (blockIdx.x * blockDim.x + threadIdx.x) >> 5;
    const int lane = threadIdx.x & 31;
    const float* hr = g_h + (size_t)w * HID;
    float v = -1e30f;
#pragma unroll
    for (int k = lane; k < HID; k += 32) v = fmaxf(v, hr[k]);
#pragma unroll
    for (int o = 16; o > 0; o >>= 1)
        v = fmaxf(v, __shfl_xor_sync(0xffffffffu, v, o));
    if (lane == 0) g_m[w] = v;
}

// ---- softmax over 4096 path logits (single block, deterministic) ----
__global__ void softmax_paths()
{
    __shared__ float red[32];
    __shared__ float bcast;
    const int tid  = threadIdx.x;
    const int lane = tid & 31, wid = tid >> 5;

    float v[4];
    float mx = -1e30f;
#pragma unroll
    for (int i = 0; i < 4; i++) {
        v[i] = g_m[tid + i * 1024];
        mx = fmaxf(mx, v[i]);
    }
#pragma unroll
    for (int o = 16; o > 0; o >>= 1)
        mx = fmaxf(mx, __shfl_xor_sync(0xffffffffu, mx, o));
    if (lane == 0) red[wid] = mx;
    __syncthreads();
    if (wid == 0) {
        float m2 = red[lane];
#pragma unroll
        for (int o = 16; o > 0; o >>= 1)
            m2 = fmaxf(m2, __shfl_xor_sync(0xffffffffu, m2, o));
        if (lane == 0) bcast = m2;
    }
    __syncthreads();
    const float MX = bcast;

    float s = 0.f;
#pragma unroll
    for (int i = 0; i < 4; i++) { v[i] = expf(v[i] - MX); s += v[i]; }
#pragma unroll
    for (int o = 16; o > 0; o >>= 1)
        s += __shfl_xor_sync(0xffffffffu, s, o);
    if (lane == 0) red[wid] = s;
    __syncthreads();
    if (wid == 0) {
        float s2 = red[lane];
#pragma unroll
        for (int o = 16; o > 0; o >>= 1)
            s2 += __shfl_xor_sync(0xffffffffu, s2, o);
        if (lane == 0) bcast = s2;
    }
    __syncthreads();
    const float inv = 1.f / bcast;
#pragma unroll
    for (int i = 0; i < 4; i++) g_a[tid + i * 1024] = v[i] * inv;
}

// ---- weighted column sum: partials per 128-path chunk (no atomics) ----
__global__ void wsum()
{
    const int col = threadIdx.x;
    const int p0  = blockIdx.x * 128;
    float acc = 0.f;
    for (int pp = 0; pp < 128; pp++) {
        const int p = p0 + pp;
        acc += g_h[(size_t)p * HID + col] * g_a[p];
    }
    g_part[blockIdx.x * HID + col] = acc;
}

// ---- final: reduce partials, concat dot with w_lin, sigmoid ----
__global__ void final_k(const float* __restrict__ emb,
                        const void* __restrict__ uid,
                        const void* __restrict__ iid,
                        const float* __restrict__ w_lin,
                        const float* __restrict__ b_lin,
                        float* __restrict__ out)
{
    __shared__ float red[256];
    const int j = threadIdx.x;
    float pe = 0.f;
#pragma unroll
    for (int b = 0; b < 32; b++) pe += g_part[b * HID + j];

    const size_t u  = (size_t)load_idx(uid, 0) * DIM;
    const size_t it = (size_t)load_idx(iid, 0) * DIM;
    float v = emb[u + j]  * w_lin[j]
            + emb[it + j] * w_lin[256 + j]
            + pe          * w_lin[512 + j];
    red[j] = v;
    __syncthreads();
#pragma unroll
    for (int s = 128; s > 0; s >>= 1) {
        if (j < s) red[j] += red[j + s];
        __syncthreads();
    }
    if (j == 0) out[0] = 1.f / (1.f + expf(-(red[0] + b_lin[0])));
}

extern "C" void kernel_launch(void* const* d_in, const int* in_sizes, int n_in,
                              void* d_out, int out_size)
{
    const float* embedding = (const float*)d_in[0];
    const float* w_ih      = (const float*)d_in[1];
    const float* w_hh      = (const float*)d_in[2];
    const float* b_ih      = (const float*)d_in[3];
    const float* b_hh      = (const float*)d_in[4];
    const float* w_lin     = (const float*)d_in[5];
    const float* b_lin     = (const float*)d_in[6];
    const void*  paths     = d_in[7];
    const void*  uid       = d_in[8];
    const void*  iid       = d_in[9];

    cudaFuncSetAttribute(mm_fused, cudaFuncAttributeMaxDynamicSharedMemorySize, SM_TOT);

    detect_idx_kernel<<<1, 1>>>(paths);                       // 0
    prep<<<6148, 256>>>(w_ih, w_hh, b_ih, b_hh);              // 1
    gather_conv<<<M1 / 4, 256>>>(embedding, paths);           // 2

    // slice(0): X[:,0,:] projection                           // 3  <- ncu lands here
    mm_fused<<<dim3(8, 32), 256, SM_TOT>>>(-1);

    // t=0..6: step(t) overlapped with slice(t+1) in one grid
    for (int t = 0; t < 7; t++)
        mm_fused<<<dim3(8, 64), 256, SM_TOT>>>(t);

    // t=7: step only
    mm_fused<<<dim3(8, 32), 256, SM_TOT>>>(7);

    // attention over paths + final linear/sigmoid
    rowmax<<<512, 256>>>();
    softmax_paths<<<1, 1024>>>();
    wsum<<<32, 256>>>();
    final_k<<<1, 256>>>(embedding, uid, iid, w_lin, b_lin, (float*)d_out);
}

// round 17
// speedup vs baseline: 1.9269x; 1.4501x over previous
#include <cuda_runtime.h>
#include <cuda_fp16.h>
#include <cstdint>

#define PATHS 4096
#define LPATH 8
#define DIM   256
#define HID   256
#define GATE  1024           // 4*HID
#define M1    (PATHS*LPATH)  // 32768
#define NODE  100000

// ---------------------------------------------------------------------------
// Scratch (static device globals; no runtime allocation)
// ---------------------------------------------------------------------------
__device__ float g_X[(size_t)M1 * GATE];        // input projections (+bias), fp32,
                                                // columns in PERMUTED gate order 4*unit+gate
__device__ float g_h[(size_t)PATHS * HID];
__device__ float g_c[(size_t)PATHS * HID];
__device__ float g_m[PATHS];
__device__ float g_a[PATHS];
__device__ float g_part[32 * HID];
__device__ float g_bias[GATE];                  // (b_ih + b_hh), permuted
__device__ int   g_is64;

// fp16 operands (K-major, row pitch = 256)
// Weight rows PERMUTED: new row = 4*unit + gate  (gate: 0=i,1=f,2=g,3=o)
__device__ __align__(256) __half g_Xh[(size_t)M1 * DIM];
__device__ __align__(256) __half g_Hh[(size_t)PATHS * HID];
__device__ __align__(256) __half g_Wih[(size_t)GATE * DIM];
__device__ __align__(256) __half g_Whh[(size_t)GATE * HID];

// ---------------------------------------------------------------------------
// PTX helpers (base-target, assembles for family-generic sm_103)
// ---------------------------------------------------------------------------
__device__ __forceinline__ uint32_t smem_to_u32(const void* p) {
    uint32_t a;
    asm("{ .reg .u64 t; cvta.to.shared.u64 t, %1; cvt.u32.u64 %0, t; }"
        : "=r"(a) : "l"(p));
    return a;
}

__device__ __forceinline__ void ldmx4(uint32_t addr, uint32_t* r) {
    asm volatile("ldmatrix.sync.aligned.m8n8.x4.shared.b16 {%0,%1,%2,%3}, [%4];"
                 : "=r"(r[0]), "=r"(r[1]), "=r"(r[2]), "=r"(r[3]) : "r"(addr));
}

__device__ __forceinline__ void mma16816(float* d, const uint32_t* a,
                                         uint32_t b0, uint32_t b1) {
    asm volatile(
        "mma.sync.aligned.m16n8k16.row.col.f32.f16.f16.f32 "
        "{%0,%1,%2,%3}, {%4,%5,%6,%7}, {%8,%9}, {%0,%1,%2,%3};"
        : "+f"(d[0]), "+f"(d[1]), "+f"(d[2]), "+f"(d[3])
        : "r"(a[0]), "r"(a[1]), "r"(a[2]), "r"(a[3]), "r"(b0), "r"(b1));
}

__device__ __forceinline__ void cpasync16(uint32_t dst, const void* src) {
    asm volatile("cp.async.cg.shared.global [%0], [%1], 16;"
                 :: "r"(dst), "l"(src) : "memory");
}
#define CP_COMMIT() asm volatile("cp.async.commit_group;" ::: "memory")
#define CP_WAIT0()  asm volatile("cp.async.wait_group 0;" ::: "memory")

// ---------------------------------------------------------------------------
// Index-dtype probe (int64 reference vs possible int32 materialization)
// ---------------------------------------------------------------------------
__global__ void detect_idx_kernel(const void* __restrict__ paths_raw)
{
    const int* a = (const int*)paths_raw;
    int ok64 = 1;
#pragma unroll
    for (int i = 0; i < 64; i += 2)
        if (a[i + 1] != 0) ok64 = 0;
    g_is64 = ok64;
}

__device__ __forceinline__ long long load_idx(const void* buf, int m)
{
    if (g_is64) return ((const long long*)buf)[m];
    return (long long)((const int*)buf)[m];
}

// ---------------------------------------------------------------------------
// prep: weights->fp16 (permuted rows), bias (permuted), zero h/c state.
// Role by blockIdx.x:
//   [0, 2048)      : conv weights (2*GATE*DIM elems)
//   [2048, 2052)   : bias perm
//   [2052, 6148)   : zero g_c / g_Hh (PATHS*HID elems)
// ---------------------------------------------------------------------------
__global__ void prep(const float* __restrict__ w_ih, const float* __restrict__ w_hh,
                     const float* __restrict__ b_ih, const float* __restrict__ b_hh)
{
    const int b = blockIdx.x;
    const int tid = threadIdx.x;
    if (b < 2048) {
        const int idx = b * 256 + tid;
        const int half_sel = idx >= GATE * DIM;
        const int j    = half_sel ? idx - GATE * DIM : idx;
        const int r    = j >> 8;
        const int c    = j & 255;
        const int newr = ((r & 255) << 2) | (r >> 8);   // 4*unit + gate
        const int dst  = (newr << 8) | c;
        if (!half_sel) g_Wih[dst] = __float2half(w_ih[j]);
        else           g_Whh[dst] = __float2half(w_hh[j]);
    } else if (b < 2052) {
        const int r = (b - 2048) * 256 + tid;
        const int newr = ((r & 255) << 2) | (r >> 8);
        g_bias[newr] = b_ih[r] + b_hh[r];
    } else {
        const int idx = (b - 2052) * 256 + tid;
        g_c[idx] = 0.f;
        g_Hh[idx] = __float2half(0.f);
    }
}

// gather embedding rows -> fp16 (float4 per thread, 4 rows per block)
__global__ void gather_conv(const float* __restrict__ emb, const void* __restrict__ paths)
{
    const int tid = threadIdx.x;              // 256
    const int m   = blockIdx.x * 4 + (tid >> 6);
    const int c4  = (tid & 63) << 2;
    const size_t row = (size_t)load_idx(paths, m);
    const float4 x = *(const float4*)(emb + row * DIM + c4);
    __half2* dh = (__half2*)(g_Xh + (size_t)m * DIM + c4);
    dh[0] = __floats2half2_rn(x.x, x.y);
    dh[1] = __floats2half2_rn(x.z, x.w);
}

// ---------------------------------------------------------------------------
// fp16 HMMA GEMM, BM=128 BN=128 KC=32, 2-stage cp.async.
//   step < 0 : A = g_Xh (rows m=0..M1), C -> g_X (+bias, permuted cols)
//   step >= 0: A = g_Hh (rows = paths), epilogue: +g_X[:,step,:] -> fused LSTM
// 256 threads (8 warps, 2x4), warp tile 64x32, smem 2 x 20KB = 40KB.
// ---------------------------------------------------------------------------
#define PITCH_B 80                     // bytes per smem row (40 halves)
#define MAT_SZ  (128 * PITCH_B)        // 10240 bytes per matrix
#define STG_SZ  (2 * MAT_SZ)           // 20480 per stage (A + B)
#define SM_TOT  (2 * STG_SZ)           // 40960
#define OFF_A   0
#define OFF_B   MAT_SZ

__device__ __forceinline__ float sigf(float x) { return 1.f / (1.f + expf(-x)); }

// Load one KC=32 chunk (A and B) into one stage. 256 threads:
// row = tid>>1 (0..127), half = tid&1 selects 32B half-row. All static.
__device__ __forceinline__ void stage_load(
    uint32_t sbase,
    const __half* __restrict__ aP, const __half* __restrict__ bP,
    size_t astr, int tid)
{
    const int row  = tid >> 1;
    const int hsel = tid & 1;
    const uint32_t rb = (uint32_t)row * PITCH_B + hsel * 32;
    const size_t ao = (size_t)row * astr + hsel * 16;
    const size_t bo = (size_t)row * 256  + hsel * 16;
    cpasync16(sbase + OFF_A + rb,      aP + ao);
    cpasync16(sbase + OFF_A + rb + 16, aP + ao + 8);
    cpasync16(sbase + OFF_B + rb,      bP + bo);
    cpasync16(sbase + OFF_B + rb + 16, bP + bo + 8);
}

__global__ void __launch_bounds__(256, 2)
mm_mma(int step)
{
    extern __shared__ char smem[];
    const uint32_t sb = smem_to_u32(smem);
    const int tid  = threadIdx.x;
    const int bx   = blockIdx.x;   // N tile (0..7), 128 cols
    const int by   = blockIdx.y;   // M tile, 128 rows

    const size_t arow0 = (size_t)by * 128;
    const size_t brow0 = (size_t)bx * 128;

    const __half *aPb, *bPb;
    if (step < 0) { aPb = g_Xh + arow0 * DIM; bPb = g_Wih + brow0 * DIM; }
    else          { aPb = g_Hh + arow0 * HID; bPb = g_Whh + brow0 * HID; }

    // ---- warp tiling: 8 warps = 2 (m) x 4 (n), warp tile 64x32 ----
    const int wid  = tid >> 5;
    const int lane = tid & 31;
    const int wm   = wid & 1;
    const int wn   = wid >> 1;         // 0..3
    const int lr   = lane & 7;
    const int lg   = lane >> 3;

    const uint32_t aoff = (uint32_t)(wm * 64 + (lg & 1) * 8 + lr) * PITCH_B + (lg >> 1) * 16;
    const uint32_t boff = (uint32_t)(wn * 32 + (lg >> 1) * 8 + lr) * PITCH_B + (lg & 1) * 16;

    float acc[4][4][4];
#pragma unroll
    for (int i = 0; i < 4; i++)
#pragma unroll
        for (int j = 0; j < 4; j++)
#pragma unroll
            for (int d = 0; d < 4; d++) acc[i][j][d] = 0.f;

    // ---- prologue: stage 0 ----
    stage_load(sb, aPb, bPb, 256, tid);
    CP_COMMIT();

    for (int kc = 0; kc < 8; kc++) {
        CP_WAIT0();
        __syncthreads();

        if (kc + 1 < 8) {
            const int k0 = (kc + 1) * 32;
            stage_load(sb + ((kc + 1) & 1) * STG_SZ, aPb + k0, bPb + k0, 256, tid);
            CP_COMMIT();
        }

        const uint32_t st = sb + (kc & 1) * STG_SZ;
#pragma unroll
        for (int k16 = 0; k16 < 2; k16++) {
            const uint32_t ko = k16 * 32;
            uint32_t a[4][4], b[2][4];
#pragma unroll
            for (int mt = 0; mt < 4; mt++)
                ldmx4(st + OFF_A + aoff + ko + mt * (16 * PITCH_B), a[mt]);
#pragma unroll
            for (int bt = 0; bt < 2; bt++)
                ldmx4(st + OFF_B + boff + ko + bt * (16 * PITCH_B), b[bt]);
#pragma unroll
            for (int mt = 0; mt < 4; mt++)
#pragma unroll
                for (int bt = 0; bt < 2; bt++)
#pragma unroll
                    for (int sub = 0; sub < 2; sub++)
                        mma16816(acc[mt][bt * 2 + sub], a[mt], b[bt][2 * sub], b[bt][2 * sub + 1]);
        }
    }

    // ---- epilogue ----
    const int lq = lane >> 2;            // row within 8
    const int lp = lane & 3;             // col pair within n8
#pragma unroll
    for (int mt = 0; mt < 4; mt++) {
#pragma unroll
        for (int nt = 0; nt < 4; nt++) {
            const int gcol = bx * 128 + wn * 32 + nt * 8 + lp * 2;
#pragma unroll
            for (int half_i = 0; half_i < 2; half_i++) {
                const int rloc = wm * 64 + mt * 16 + lq + half_i * 8;
                const size_t m = arow0 + rloc;
                float v0 = acc[mt][nt][half_i * 2 + 0];
                float v1 = acc[mt][nt][half_i * 2 + 1];
                if (step < 0) {
                    v0 += g_bias[gcol];
                    v1 += g_bias[gcol + 1];
                    *(float2*)(g_X + m * GATE + gcol) = make_float2(v0, v1);
                } else {
                    const float2 ad = *(const float2*)(g_X + (m * LPATH + step) * GATE + gcol);
                    v0 += ad.x;
                    v1 += ad.y;
                    // assemble (i,f,g,o) quad across lane pair (lp even: i,f / odd: g,o)
                    const float w0 = __shfl_xor_sync(0xffffffffu, v0, 1);
                    const float w1 = __shfl_xor_sync(0xffffffffu, v1, 1);
                    float iv, fv, gv, ov;
                    if (lp & 1) { iv = w0; fv = w1; gv = v0; ov = v1; }
                    else        { iv = v0; fv = v1; gv = w0; ov = w1; }
                    const int unit = gcol >> 2;           // same for both lanes of pair
                    const size_t idx = m * HID + unit;
                    const float cold = g_c[idx];
                    const float cnew = sigf(fv) * cold + sigf(iv) * tanhf(gv);
                    const float h    = sigf(ov) * tanhf(cnew);
                    if (lp & 1) {
                        g_Hh[idx] = __float2half(h);
                    } else {
                        g_c[idx] = cnew;
                        g_h[idx] = h;
                    }
                }
            }
        }
    }
}

// ---- row-max over hidden dim: one warp per path ----
__global__ void rowmax()
{
    const int w    = (blockIdx.x * blockDim.x + threadIdx.x) >> 5;
    const int lane = threadIdx.x & 31;
    const float* hr = g_h + (size_t)w * HID;
    float v = -1e30f;
#pragma unroll
    for (int k = lane; k < HID; k += 32) v = fmaxf(v, hr[k]);
#pragma unroll
    for (int o = 16; o > 0; o >>= 1)
        v = fmaxf(v, __shfl_xor_sync(0xffffffffu, v, o));
    if (lane == 0) g_m[w] = v;
}

// ---- softmax over 4096 path logits (single block, deterministic) ----
__global__ void softmax_paths()
{
    __shared__ float red[32];
    __shared__ float bcast;
    const int tid  = threadIdx.x;
    const int lane = tid & 31, wid = tid >> 5;

    float v[4];
    float mx = -1e30f;
#pragma unroll
    for (int i = 0; i < 4; i++) {
        v[i] = g_m[tid + i * 1024];
        mx = fmaxf(mx, v[i]);
    }
#pragma unroll
    for (int o = 16; o > 0; o >>= 1)
        mx = fmaxf(mx, __shfl_xor_sync(0xffffffffu, mx, o));
    if (lane == 0) red[wid] = mx;
    __syncthreads();
    if (wid == 0) {
        float m2 = red[lane];
#pragma unroll
        for (int o = 16; o > 0; o >>= 1)
            m2 = fmaxf(m2, __shfl_xor_sync(0xffffffffu, m2, o));
        if (lane == 0) bcast = m2;
    }
    __syncthreads();
    const float MX = bcast;

    float s = 0.f;
#pragma unroll
    for (int i = 0; i < 4; i++) { v[i] = expf(v[i] - MX); s += v[i]; }
#pragma unroll
    for (int o = 16; o > 0; o >>= 1)
        s += __shfl_xor_sync(0xffffffffu, s, o);
    if (lane == 0) red[wid] = s;
    __syncthreads();
    if (wid == 0) {
        float s2 = red[lane];
#pragma unroll
        for (int o = 16; o > 0; o >>= 1)
            s2 += __shfl_xor_sync(0xffffffffu, s2, o);
        if (lane == 0) bcast = s2;
    }
    __syncthreads();
    const float inv = 1.f / bcast;
#pragma unroll
    for (int i = 0; i < 4; i++) g_a[tid + i * 1024] = v[i] * inv;
}

// ---- weighted column sum: partials per 128-path chunk (no atomics) ----
__global__ void wsum()
{
    const int col = threadIdx.x;
    const int p0  = blockIdx.x * 128;
    float acc = 0.f;
    for (int pp = 0; pp < 128; pp++) {
        const int p = p0 + pp;
        acc += g_h[(size_t)p * HID + col] * g_a[p];
    }
    g_part[blockIdx.x * HID + col] = acc;
}

// ---- final: reduce partials, concat dot with w_lin, sigmoid ----
__global__ void final_k(const float* __restrict__ emb,
                        const void* __restrict__ uid,
                        const void* __restrict__ iid,
                        const float* __restrict__ w_lin,
                        const float* __restrict__ b_lin,
                        float* __restrict__ out)
{
    __shared__ float red[256];
    const int j = threadIdx.x;
    float pe = 0.f;
#pragma unroll
    for (int b = 0; b < 32; b++) pe += g_part[b * HID + j];

    const size_t u  = (size_t)load_idx(uid, 0) * DIM;
    const size_t it = (size_t)load_idx(iid, 0) * DIM;
    float v = emb[u + j]  * w_lin[j]
            + emb[it + j] * w_lin[256 + j]
            + pe          * w_lin[512 + j];
    red[j] = v;
    __syncthreads();
#pragma unroll
    for (int s = 128; s > 0; s >>= 1) {
        if (j < s) red[j] += red[j + s];
        __syncthreads();
    }
    if (j == 0) out[0] = 1.f / (1.f + expf(-(red[0] + b_lin[0])));
}

extern "C" void kernel_launch(void* const* d_in, const int* in_sizes, int n_in,
                              void* d_out, int out_size)
{
    const float* embedding = (const float*)d_in[0];
    const float* w_ih      = (const float*)d_in[1];
    const float* w_hh      = (const float*)d_in[2];
    const float* b_ih      = (const float*)d_in[3];
    const float* b_hh      = (const float*)d_in[4];
    const float* w_lin     = (const float*)d_in[5];
    const float* b_lin     = (const float*)d_in[6];
    const void*  paths     = d_in[7];
    const void*  uid       = d_in[8];
    const void*  iid       = d_in[9];

    cudaFuncSetAttribute(mm_mma, cudaFuncAttributeMaxDynamicSharedMemorySize, SM_TOT);

    detect_idx_kernel<<<1, 1>>>(paths);                       // 0
    prep<<<6148, 256>>>(w_ih, w_hh, b_ih, b_hh);              // 1
    gather_conv<<<M1 / 4, 256>>>(embedding, paths);           // 2

    // X = embedding[paths] @ w_ih^T + bias   [32768, 1024] (permuted cols)
    mm_mma<<<dim3(8, M1 / 128), 256, SM_TOT>>>(-1);           // 3 <- ncu lands here

    // 8 recurrent steps: gates = X[:,t] + h @ w_hh^T, LSTM fused in epilogue
    for (int t = 0; t < LPATH; t++)
        mm_mma<<<dim3(8, PATHS / 128), 256, SM_TOT>>>(t);

    // attention over paths + final linear/sigmoid
    rowmax<<<512, 256>>>();
    softmax_paths<<<1, 1024>>>();
    wsum<<<32, 256>>>();
    final_k<<<1, 256>>>(embedding, uid, iid, w_lin, b_lin, (float*)d_out);
}